// round 11
// baseline (speedup 1.0000x reference)
#include <cuda_runtime.h>
#include <cuda_bf16.h>
#include <cuda_fp16.h>
#include <math.h>
#include <stdint.h>

#define B_  512
#define S_  512
#define DI_ 256
#define DO_ 256

// fp16-packed Wh A-fragments: [g(=t*8+kh*4+c)][wm(8)][s2(2)][mt(2)][lane(32)] float4(=8 f16).
__device__ float4 WhP_h[(size_t)S_ * 8 * 8 * 128];
// producer->consumer flags: flagZ_g[t] counts completed phase-1 tiles (4 per t)
__device__ int flagZ_g[S_];

// ---------------- helpers ----------------

__device__ __forceinline__ void cpasync16(void* smem_dst, const void* gsrc) {
    unsigned saddr = (unsigned)__cvta_generic_to_shared(smem_dst);
    asm volatile("cp.async.cg.shared.global [%0], [%1], 16;\n" :: "r"(saddr), "l"(gsrc));
}
__device__ __forceinline__ void cp_commit() { asm volatile("cp.async.commit_group;\n"); }
template <int N> __device__ __forceinline__ void cp_wait() {
    asm volatile("cp.async.wait_group %0;\n" :: "n"(N));
}
__device__ __forceinline__ unsigned f2u(float f) { return __float_as_uint(f); }
__device__ __forceinline__ float fast_tanh(float x) {
    float e = __expf(2.0f * x);
    return 1.0f - __fdividef(2.0f, e + 1.0f);
}
__device__ __forceinline__ uint32_t smem_u32(const void* p) {
    return (uint32_t)__cvta_generic_to_shared(p);
}
__device__ __forceinline__ uint32_t packh2(float a, float b) {
    __half2 h = __floats2half2_rn(a, b);
    return *(uint32_t*)&h;
}
__device__ __forceinline__ int ld_acquire(const int* p) {
    int v;
    asm volatile("ld.acquire.gpu.global.s32 %0, [%1];" : "=r"(v) : "l"(p) : "memory");
    return v;
}
__device__ __forceinline__ void red_release_add(int* p, int v) {
    asm volatile("red.release.gpu.global.add.s32 [%0], %1;" :: "l"(p), "r"(v) : "memory");
}

__device__ __forceinline__ void mma_tf32(float c[4],
                                         unsigned a0, unsigned a1, unsigned a2, unsigned a3,
                                         unsigned b0, unsigned b1) {
    asm volatile(
        "mma.sync.aligned.m16n8k8.row.col.f32.tf32.tf32.f32 "
        "{%0,%1,%2,%3}, {%4,%5,%6,%7}, {%8,%9}, {%0,%1,%2,%3};\n"
        : "+f"(c[0]), "+f"(c[1]), "+f"(c[2]), "+f"(c[3])
        : "r"(a0), "r"(a1), "r"(a2), "r"(a3), "r"(b0), "r"(b1));
}
__device__ __forceinline__ void mma_f16(float c[4],
                                        unsigned a0, unsigned a1, unsigned a2, unsigned a3,
                                        unsigned b0, unsigned b1) {
    asm volatile(
        "mma.sync.aligned.m16n8k16.row.col.f32.f16.f16.f32 "
        "{%0,%1,%2,%3}, {%4,%5,%6,%7}, {%8,%9}, {%0,%1,%2,%3};\n"
        : "+f"(c[0]), "+f"(c[1]), "+f"(c[2]), "+f"(c[3])
        : "r"(a0), "r"(a1), "r"(a2), "r"(a3), "r"(b0), "r"(b1));
}

#define LDSM_X4(r0, r1, r2, r3, addr) \
    asm volatile("ldmatrix.sync.aligned.m8n8.x4.shared.b16 {%0,%1,%2,%3}, [%4];" \
                 : "=r"(r0), "=r"(r1), "=r"(r2), "=r"(r3) : "r"(addr))

// ---------------- Phase 0: pack Wh -> fp16 fragments + zero flags ----------------

__global__ __launch_bounds__(256, 1) void prepack_wh(const float* __restrict__ Wh)
{
    __shared__ float tile[32 * 260];
    const int slab = blockIdx.x;
    const int t    = blockIdx.y;
    const int tid  = threadIdx.x;

    if (slab == 0 && t == 0) {
        for (int i = tid; i < S_; i += 256) flagZ_g[i] = 0;
    }

    const float* src = Wh + (size_t)t * (DO_ * DO_) + (size_t)slab * 32 * DO_;
#pragma unroll
    for (int j = 0; j < 8; j++) {
        int idx = tid + j * 256;
        int r = idx >> 6, q = idx & 63;
        *(float4*)&tile[r * 260 + q * 4] = *(const float4*)&src[r * DO_ + q * 4];
    }
    __syncthreads();

    const size_t g = (size_t)t * 8 + slab;
#pragma unroll
    for (int j = 0; j < 4; j++) {
        int idx  = tid + j * 256;
        int lane = idx & 31;
        int mt   = (idx >> 5) & 1;
        int s2   = (idx >> 6) & 1;
        int wm   = (idx >> 7) & 7;
        int r    = lane >> 2, cc = (lane & 3) * 2;
        int m0   = wm * 32 + mt * 16 + r;
        int kk   = s2 * 16 + cc;
        float4 v;
        v.x = __uint_as_float(packh2(tile[kk * 260 + m0],       tile[(kk + 1) * 260 + m0]));
        v.y = __uint_as_float(packh2(tile[kk * 260 + m0 + 8],   tile[(kk + 1) * 260 + m0 + 8]));
        v.z = __uint_as_float(packh2(tile[(kk + 8) * 260 + m0], tile[(kk + 9) * 260 + m0]));
        v.w = __uint_as_float(packh2(tile[(kk + 8) * 260 + m0 + 8], tile[(kk + 9) * 260 + m0 + 8]));
        WhP_h[(g * 8 + wm) * 128 + (s2 * 2 + mt) * 32 + lane] = v;
    }
}

// ---------------- Fused kernel: phase-1 workers + phase-2 consumers ----------------
// Grid = #SMs, 512 thr, 1 CTA/SM (smem-forced) -> all CTAs wave-1 resident.
//   bid <  64 : phase-2 consumer, batch rows [bid*8, bid*8+8), waits flagZ_g[t]==4.
//   bid >= 64 : phase-1 worker; tiles (t, mslice) = (tile>>2, tile&3), tile = wid + i*nw.
// Worker tile: Z[m_base..+128, t, 0..256] = x_tile @ Wx[t], tf32, 16 warps (wm 4 x wn 4).

#define FK_AS   (128 * 36)
#define FK_BS   (32 * 260)
#define FK_SMEM ((2 * FK_AS + 2 * FK_BS) * 4)   // 103,424 B
#define P2_HSTR 264

__global__ __launch_bounds__(512, 1) void rnn_fused(
    const float* __restrict__ x, const float* __restrict__ Wx, float* __restrict__ out)
{
    extern __shared__ float smf[];
    const int tid  = threadIdx.x;
    const int w    = tid >> 5, lane = tid & 31;
    const int grp  = lane >> 2, tig = lane & 3;

    if (blockIdx.x >= 64) {
        // ---------------- phase-1 worker ----------------
        float* As[2] = { smf, smf + FK_AS };
        float* Bs[2] = { smf + 2 * FK_AS, smf + 2 * FK_AS + FK_BS };
        const int wid = blockIdx.x - 64;
        const int nw  = gridDim.x - 64;
        const int wm = w & 3, wn = w >> 2;

        for (int tile = wid; tile < 4 * S_; tile += nw) {
            const int t      = tile >> 2;
            const int m_base = (tile & 3) * 128;

            auto loadChunk = [&](int kc, int buf) {
#pragma unroll
                for (int j = 0; j < 2; j++) {
                    int i = tid + j * 512;
                    int r = i >> 3, q = i & 7;
                    cpasync16(&As[buf][r * 36 + q * 4],
                              x + ((size_t)(m_base + r) * S_ + t) * DI_ + kc * 32 + q * 4);
                }
#pragma unroll
                for (int j = 0; j < 4; j++) {
                    int i = tid + j * 512;
                    int k = i >> 6, q = i & 63;
                    cpasync16(&Bs[buf][k * 260 + q * 4],
                              Wx + (size_t)t * (DI_ * DO_) + (size_t)(kc * 32 + k) * DO_ + q * 4);
                }
                cp_commit();
            };

            float acc[2][8][4];
#pragma unroll
            for (int mt = 0; mt < 2; mt++)
#pragma unroll
                for (int nt = 0; nt < 8; nt++)
#pragma unroll
                    for (int i = 0; i < 4; i++) acc[mt][nt][i] = 0.f;

            loadChunk(0, 0);
            loadChunk(1, 1);

            for (int kc = 0; kc < 8; kc++) {
                if (kc < 7) cp_wait<1>(); else cp_wait<0>();
                __syncthreads();
                const int buf = kc & 1;
                const float* A = As[buf];
                const float* Bsm = Bs[buf];
#pragma unroll
                for (int ks = 0; ks < 4; ks++) {
                    const int k = ks * 8;
                    unsigned a[2][4];
#pragma unroll
                    for (int mt = 0; mt < 2; mt++) {
                        const int rb = wm * 32 + mt * 16;
                        a[mt][0] = f2u(A[(rb + grp)     * 36 + k + tig]);
                        a[mt][1] = f2u(A[(rb + grp + 8) * 36 + k + tig]);
                        a[mt][2] = f2u(A[(rb + grp)     * 36 + k + 4 + tig]);
                        a[mt][3] = f2u(A[(rb + grp + 8) * 36 + k + 4 + tig]);
                    }
#pragma unroll
                    for (int nt = 0; nt < 8; nt++) {
                        const int cb = wn * 64 + nt * 8 + grp;
                        unsigned b0 = f2u(Bsm[(k + tig)     * 260 + cb]);
                        unsigned b1 = f2u(Bsm[(k + 4 + tig) * 260 + cb]);
#pragma unroll
                        for (int mt = 0; mt < 2; mt++)
                            mma_tf32(acc[mt][nt], a[mt][0], a[mt][1], a[mt][2], a[mt][3], b0, b1);
                    }
                }
                __syncthreads();
                if (kc + 2 < 8) loadChunk(kc + 2, buf);
            }

            // store Z
#pragma unroll
            for (int mt = 0; mt < 2; mt++) {
#pragma unroll
                for (int nt = 0; nt < 8; nt++) {
                    const int row = m_base + wm * 32 + mt * 16 + grp;
                    const int col = wn * 64 + nt * 8 + 2 * tig;
                    const size_t g0 = ((size_t)row * S_ + t) * DO_ + col;
                    float2 v0; v0.x = acc[mt][nt][0]; v0.y = acc[mt][nt][1];
                    *(float2*)&out[g0] = v0;
                    const size_t g1 = ((size_t)(row + 8) * S_ + t) * DO_ + col;
                    float2 v1; v1.x = acc[mt][nt][2]; v1.y = acc[mt][nt][3];
                    *(float2*)&out[g1] = v1;
                }
            }

            __threadfence();          // make this thread's Z stores gpu-visible
            __syncthreads();          // all threads' fences done
            if (tid == 0) red_release_add(&flagZ_g[t], 1);
        }
        return;
    }

    // ---------------- phase-2 consumer (R10 structure + flag gating) ----------------
    __half* hs2  = (__half*)smf;                                   // 8*264 halfs = 4224 B
    float4 (*scr)[8][32] = (float4(*)[8][32])((char*)smf + 4224);  // 2*8*32 f4 = 8192 B

    const int kh   = w >> 3, wm = w & 7;
    const int brow = blockIdx.x * 8;
    const int m0   = wm * 32 + kh * 16 + grp;
    const int n0   = 2 * tig;

    for (int i = tid; i < 8 * P2_HSTR / 2; i += 512) ((uint32_t*)hs2)[i] = 0u;
    if (tid == 0) {
        while (ld_acquire(&flagZ_g[0]) < 4) __nanosleep(64);
    }
    __syncthreads();

    const uint32_t hs_base = smem_u32(hs2);
    const uint32_t lmb = hs_base + (uint32_t)(lane & 7) * (P2_HSTR * 2) + (uint32_t)(lane >> 3) * 16;

    float4 A[2][2][2];
    auto ldA = [&](int s, int st) {
        const int g = ((s >> 2) << 3) | (kh << 2) | (s & 3);
        const size_t base = ((size_t)g * 8 + wm) * 128 + lane;
        A[st][0][0] = __ldg(&WhP_h[base]);
        A[st][0][1] = __ldg(&WhP_h[base + 32]);
        A[st][1][0] = __ldg(&WhP_h[base + 64]);
        A[st][1][1] = __ldg(&WhP_h[base + 96]);
    };
    ldA(0, 0);
    ldA(1, 1);

    float acc[2][4];
    float z[4];
    int s = 0;

    for (int t = 0; t < S_; t++) {
#pragma unroll
        for (int mt = 0; mt < 2; mt++)
#pragma unroll
            for (int i = 0; i < 4; i++) acc[mt][i] = 0.f;

        // Z loads (flag[t] already verified before entering step t)
        z[0] = out[((size_t)(brow + n0)     * S_ + t) * DO_ + m0];
        z[1] = out[((size_t)(brow + n0 + 1) * S_ + t) * DO_ + m0];
        z[2] = out[((size_t)(brow + n0)     * S_ + t) * DO_ + m0 + 8];
        z[3] = out[((size_t)(brow + n0 + 1) * S_ + t) * DO_ + m0 + 8];

        for (int c = 0; c < 4; c++) {
            const int st = s & 1;
            const int k0 = kh * 128 + c * 32;
            uint32_t b0, b1, b2, b3;
            LDSM_X4(b0, b1, b2, b3, lmb + (uint32_t)k0 * 2);
            {
                const float4 af0 = A[st][0][0];
                mma_f16(acc[0], f2u(af0.x), f2u(af0.y), f2u(af0.z), f2u(af0.w), b0, b1);
                const float4 af1 = A[st][0][1];
                mma_f16(acc[1], f2u(af1.x), f2u(af1.y), f2u(af1.z), f2u(af1.w), b0, b1);
            }
            {
                const float4 af0 = A[st][1][0];
                mma_f16(acc[0], f2u(af0.x), f2u(af0.y), f2u(af0.z), f2u(af0.w), b2, b3);
                const float4 af1 = A[st][1][1];
                mma_f16(acc[1], f2u(af1.x), f2u(af1.y), f2u(af1.z), f2u(af1.w), b2, b3);
            }
            if (s + 2 < 4 * S_) ldA(s + 2, st);
            s++;
        }

        if (kh == 0) {
            (*scr)[wm][lane] = make_float4(acc[1][0], acc[1][1], acc[1][2], acc[1][3]);
        } else {
            scr[1][wm][lane] = make_float4(acc[0][0], acc[0][1], acc[0][2], acc[0][3]);
        }
        __syncthreads();

        const float4 p = scr[kh ^ 1][wm][lane];
        const float h0 = fast_tanh(z[0] + acc[kh][0] + p.x);
        const float h1 = fast_tanh(z[1] + acc[kh][1] + p.y);
        const float h2 = fast_tanh(z[2] + acc[kh][2] + p.z);
        const float h3 = fast_tanh(z[3] + acc[kh][3] + p.w);

        out[((size_t)(brow + n0)     * S_ + t) * DO_ + m0]     = h0;
        out[((size_t)(brow + n0 + 1) * S_ + t) * DO_ + m0]     = h1;
        out[((size_t)(brow + n0)     * S_ + t) * DO_ + m0 + 8] = h2;
        out[((size_t)(brow + n0 + 1) * S_ + t) * DO_ + m0 + 8] = h3;

        hs2[n0 * P2_HSTR + m0]           = __float2half_rn(h0);
        hs2[(n0 + 1) * P2_HSTR + m0]     = __float2half_rn(h1);
        hs2[n0 * P2_HSTR + m0 + 8]       = __float2half_rn(h2);
        hs2[(n0 + 1) * P2_HSTR + m0 + 8] = __float2half_rn(h3);

        // fold next-step flag wait into the end-of-step barrier
        if (tid == 0 && t + 1 < S_) {
            while (ld_acquire(&flagZ_g[t + 1]) < 4) __nanosleep(64);
        }
        __syncthreads();
    }
}

// ---------------- launch ----------------

extern "C" void kernel_launch(void* const* d_in, const int* in_sizes, int n_in,
                              void* d_out, int out_size)
{
    const float* x  = (const float*)d_in[0];   // [B, S, DI]
    const float* Wx = (const float*)d_in[1];   // [S, DI, DO]
    const float* Wh = (const float*)d_in[2];   // [S, DO, DO]
    float* out = (float*)d_out;                // [B, S, DO]

    int nsm = 148;
    cudaDeviceGetAttribute(&nsm, cudaDevAttrMultiProcessorCount, 0);

    cudaFuncSetAttribute(rnn_fused, cudaFuncAttributeMaxDynamicSharedMemorySize, FK_SMEM);

    prepack_wh<<<dim3(8, S_), 256>>>(Wh);
    rnn_fused<<<nsm, 512, FK_SMEM>>>(x, Wx, out);
}